// round 4
// baseline (speedup 1.0000x reference)
#include <cuda_runtime.h>

#define TPB 128
#define CELLS_PER_BLOCK 128
#define FLOATS_PER_BLOCK (CELLS_PER_BLOCK * 26)   // 3328
#define F4_PER_BLOCK (FLOATS_PER_BLOCK / 4)       // 832
#define MAX_BLOCKS 8192

__device__ float g_partials[MAX_BLOCKS];
__device__ unsigned int g_count = 0;

__device__ __forceinline__ float compute_iou(float bx, float by, float bw, float bh,
                                             float lx, float ly, float lw, float lh) {
    const float invS = 1.0f / 7.0f;
    float x1 = bx * invS - bw * 0.5f;
    float y1 = by * invS - bh * 0.5f;
    float x2 = bx * invS + bw * 0.5f;
    float y2 = by * invS + bh * 0.5f;
    float u1 = lx * invS - lw * 0.5f;
    float v1 = ly * invS - lh * 0.5f;
    float u2 = lx * invS + lw * 0.5f;
    float v2 = ly * invS + lh * 0.5f;
    float a1 = (x2 - x1) * (y2 - y1);
    float a2 = (u2 - u1) * (v2 - v1);
    float left   = fmaxf(x1, u1);
    float right  = fminf(x2, u2);
    float top    = fmaxf(y1, v1);
    float bottom = fminf(y2, v2);
    bool valid = (left < right) && (top < bottom);
    float inter = valid ? (right - left) * (bottom - top) : 0.0f;
    float uni = a1 + a2 - inter;
    return valid ? (inter / uni) : 0.0f;
}

__global__ void __launch_bounds__(TPB)
yolo_fused_kernel(const float* __restrict__ predict,
                  const float* __restrict__ label,
                  int ncells, float invN,
                  float* __restrict__ out) {
    __shared__ float sp[FLOATS_PER_BLOCK];
    __shared__ float sl[FLOATS_PER_BLOCK];
    __shared__ float sm[TPB / 32];
    __shared__ bool s_last;

    const int tid = threadIdx.x;
    const int block_cell0 = blockIdx.x * CELLS_PER_BLOCK;
    const int cells_here = min(CELLS_PER_BLOCK, ncells - block_cell0);

    // ---- coalesced staging: global -> shared via float4 ----
    if (cells_here == CELLS_PER_BLOCK) {
        const float4* gp = reinterpret_cast<const float4*>(predict + (size_t)block_cell0 * 26);
        const float4* gl = reinterpret_cast<const float4*>(label   + (size_t)block_cell0 * 26);
        float4* s4p = reinterpret_cast<float4*>(sp);
        float4* s4l = reinterpret_cast<float4*>(sl);
#pragma unroll
        for (int i = 0; i < 6; i++) {
            s4p[tid + i * TPB] = __ldg(gp + tid + i * TPB);
            s4l[tid + i * TPB] = __ldg(gl + tid + i * TPB);
        }
        // remaining 832 - 768 = 64 float4s
        if (tid < F4_PER_BLOCK - 6 * TPB) {
            s4p[tid + 6 * TPB] = __ldg(gp + tid + 6 * TPB);
            s4l[tid + 6 * TPB] = __ldg(gl + tid + 6 * TPB);
        }
    } else {
        // tail block (not hit for this shape): scalar guarded loads
        int nfl = cells_here * 26;
        const float* gp = predict + (size_t)block_cell0 * 26;
        const float* gl = label   + (size_t)block_cell0 * 26;
        for (int i = tid; i < nfl; i += TPB) {
            sp[i] = __ldg(gp + i);
            sl[i] = __ldg(gl + i);
        }
    }
    __syncthreads();

    // ---- per-cell loss from shared memory ----
    float loss = 0.0f;
    if (tid < cells_here) {
        const float* p = sp + tid * 26;
        const float* l = sl + tid * 26;

        float l4 = l[4];
        float p4 = p[4];
        float p9 = p[9];

        if (l4 == 0.0f) {
            loss = 0.5f * (p4 * p4 + p9 * p9);
        } else {
            float cls = 0.0f;
#pragma unroll
            for (int j = 10; j < 26; j++) {
                float d = p[j] - l[j];
                cls += d * d;
            }

            float iou1 = compute_iou(p[0], p[1], p[2], p[3], l[0], l[1], l[2], l[3]);
            float iou2 = compute_iou(p[5], p[6], p[7], p[8], l[0], l[1], l[2], l[3]);
            bool pick1 = iou1 > iou2;

            float s0 = pick1 ? p[0] : p[5];
            float s1 = pick1 ? p[1] : p[6];
            float s2 = pick1 ? p[2] : p[7];
            float s3 = pick1 ? p[3] : p[8];

            float d0 = s0 - l[0];
            float d1 = s1 - l[1];
            float d2 = sqrtf(s2) - sqrtf(l[2]);
            float d3 = sqrtf(s3) - sqrtf(l[3]);
            float coord_cell = d0 * d0 + d1 * d1 + d2 * d2 + d3 * d3;

            float c  = pick1 ? p4 : p9;
            float io = pick1 ? iou1 : iou2;
            float dc = c - io;
            float obj_c_cell = dc * dc;

            float other = pick1 ? p9 : p4;
            float noobj_extra = other * other;

            loss = 5.0f * coord_cell + obj_c_cell + 0.5f * noobj_extra + cls;
        }
    }

    // ---- block reduction ----
    float s = loss;
#pragma unroll
    for (int o = 16; o > 0; o >>= 1)
        s += __shfl_down_sync(0xFFFFFFFFu, s, o);
    if ((tid & 31) == 0)
        sm[tid >> 5] = s;
    __syncthreads();
    if (tid < 32) {
        s = (tid < (TPB / 32)) ? sm[tid] : 0.0f;
#pragma unroll
        for (int o = 16; o > 0; o >>= 1)
            s += __shfl_down_sync(0xFFFFFFFFu, s, o);
        if (tid == 0) {
            g_partials[blockIdx.x] = s;
            __threadfence();
            unsigned int old = atomicInc(&g_count, gridDim.x - 1);
            s_last = (old == gridDim.x - 1);
        }
    }
    __syncthreads();

    // ---- last block: deterministic final reduction ----
    if (s_last) {
        float t = 0.0f;
        for (int i = tid; i < (int)gridDim.x; i += TPB)
            t += g_partials[i];
#pragma unroll
        for (int o = 16; o > 0; o >>= 1)
            t += __shfl_down_sync(0xFFFFFFFFu, t, o);
        if ((tid & 31) == 0)
            sm[tid >> 5] = t;
        __syncthreads();
        if (tid < 32) {
            t = (tid < (TPB / 32)) ? sm[tid] : 0.0f;
#pragma unroll
            for (int o = 16; o > 0; o >>= 1)
                t += __shfl_down_sync(0xFFFFFFFFu, t, o);
            if (tid == 0)
                out[0] = t * invN;
        }
    }
}

extern "C" void kernel_launch(void* const* d_in, const int* in_sizes, int n_in,
                              void* d_out, int out_size) {
    const float* predict = (const float*)d_in[0];
    const float* label   = (const float*)d_in[1];
    float* out = (float*)d_out;

    int total  = in_sizes[0];          // B*7*7*26
    int ncells = total / 26;           // B*49
    int nblocks = (ncells + CELLS_PER_BLOCK - 1) / CELLS_PER_BLOCK;
    if (nblocks > MAX_BLOCKS) nblocks = MAX_BLOCKS;  // never hit for this shape

    float invN = 49.0f / (float)ncells;  // 1 / batch

    yolo_fused_kernel<<<nblocks, TPB>>>(predict, label, ncells, invN, out);
}

// round 5
// speedup vs baseline: 1.4485x; 1.4485x over previous
#include <cuda_runtime.h>

#define TPB 256
#define MAX_BLOCKS 8192

__device__ float g_partials[MAX_BLOCKS];

__device__ __forceinline__ float compute_iou(float bx, float by, float bw, float bh,
                                             float lx, float ly, float lw, float lh) {
    const float invS = 1.0f / 7.0f;
    float x1 = bx * invS - bw * 0.5f;
    float y1 = by * invS - bh * 0.5f;
    float x2 = bx * invS + bw * 0.5f;
    float y2 = by * invS + bh * 0.5f;
    float u1 = lx * invS - lw * 0.5f;
    float v1 = ly * invS - lh * 0.5f;
    float u2 = lx * invS + lw * 0.5f;
    float v2 = ly * invS + lh * 0.5f;
    float a1 = (x2 - x1) * (y2 - y1);
    float a2 = (u2 - u1) * (v2 - v1);
    float left   = fmaxf(x1, u1);
    float right  = fminf(x2, u2);
    float top    = fmaxf(y1, v1);
    float bottom = fminf(y2, v2);
    bool valid = (left < right) && (top < bottom);
    float inter = valid ? (right - left) * (bottom - top) : 0.0f;
    float uni = a1 + a2 - inter;
    return valid ? (inter / uni) : 0.0f;
}

__global__ void __launch_bounds__(TPB)
yolo_cell_kernel(const float* __restrict__ predict,
                 const float* __restrict__ label,
                 int ncells) {
    int cell = blockIdx.x * blockDim.x + threadIdx.x;
    float loss = 0.0f;

    if (cell < ncells) {
        const float* pbase = predict + (size_t)cell * 26;
        const float* lbase = label   + (size_t)cell * 26;

        float l4 = __ldg(lbase + 4);
        float p4 = __ldg(pbase + 4);
        float p9 = __ldg(pbase + 9);

        if (l4 == 0.0f) {
            // noobj cell (~96%)
            loss = 0.5f * (p4 * p4 + p9 * p9);
        } else {
            // coord cell (~4%) — float2 streaming, no local arrays, no spills
            const float2* pp = reinterpret_cast<const float2*>(pbase);
            const float2* lp = reinterpret_cast<const float2*>(lbase);

            float2 p01 = __ldg(pp + 0);
            float2 p23 = __ldg(pp + 1);
            float2 p45 = __ldg(pp + 2);
            float2 p67 = __ldg(pp + 3);
            float2 p89 = __ldg(pp + 4);
            float2 l01 = __ldg(lp + 0);
            float2 l23 = __ldg(lp + 1);

            float cls = 0.0f;
#pragma unroll
            for (int j = 5; j < 13; j++) {
                float2 pv = __ldg(pp + j);
                float2 lv = __ldg(lp + j);
                float dx = pv.x - lv.x;
                float dy = pv.y - lv.y;
                cls += dx * dx + dy * dy;
            }

            float iou1 = compute_iou(p01.x, p01.y, p23.x, p23.y,
                                     l01.x, l01.y, l23.x, l23.y);
            float iou2 = compute_iou(p45.y, p67.x, p67.y, p89.x,
                                     l01.x, l01.y, l23.x, l23.y);
            bool pick1 = iou1 > iou2;

            float s0 = pick1 ? p01.x : p45.y;
            float s1 = pick1 ? p01.y : p67.x;
            float s2 = pick1 ? p23.x : p67.y;
            float s3 = pick1 ? p23.y : p89.x;

            float d0 = s0 - l01.x;
            float d1 = s1 - l01.y;
            float d2 = sqrtf(s2) - sqrtf(l23.x);
            float d3 = sqrtf(s3) - sqrtf(l23.y);
            float coord_cell = d0 * d0 + d1 * d1 + d2 * d2 + d3 * d3;

            float c  = pick1 ? p45.x : p89.y;
            float io = pick1 ? iou1  : iou2;
            float dc = c - io;
            float obj_c_cell = dc * dc;

            float other = pick1 ? p89.y : p45.x;
            float noobj_extra = other * other;

            loss = 5.0f * coord_cell + obj_c_cell + 0.5f * noobj_extra + cls;
        }
    }

    // ---- block reduction ----
    __shared__ float sm[TPB / 32];
    float s = loss;
#pragma unroll
    for (int o = 16; o > 0; o >>= 1)
        s += __shfl_down_sync(0xFFFFFFFFu, s, o);
    if ((threadIdx.x & 31) == 0)
        sm[threadIdx.x >> 5] = s;
    __syncthreads();
    if (threadIdx.x < 32) {
        s = (threadIdx.x < (TPB / 32)) ? sm[threadIdx.x] : 0.0f;
#pragma unroll
        for (int o = 16; o > 0; o >>= 1)
            s += __shfl_down_sync(0xFFFFFFFFu, s, o);
        if (threadIdx.x == 0)
            g_partials[blockIdx.x] = s;
    }
}

__global__ void yolo_reduce_kernel(float* __restrict__ out, int nblocks, float invN) {
    __shared__ float sm[32];
    // nblocks is a multiple of 4 for this shape; guard anyway
    int nf4 = nblocks >> 2;
    const float4* p4 = reinterpret_cast<const float4*>(g_partials);
    float s = 0.0f;
    for (int i = threadIdx.x; i < nf4; i += blockDim.x) {
        float4 v = p4[i];
        s += (v.x + v.y) + (v.z + v.w);
    }
    for (int i = (nf4 << 2) + threadIdx.x; i < nblocks; i += blockDim.x)
        s += g_partials[i];
#pragma unroll
    for (int o = 16; o > 0; o >>= 1)
        s += __shfl_down_sync(0xFFFFFFFFu, s, o);
    if ((threadIdx.x & 31) == 0)
        sm[threadIdx.x >> 5] = s;
    __syncthreads();
    if (threadIdx.x < 32) {
        s = (threadIdx.x < (int)(blockDim.x >> 5)) ? sm[threadIdx.x] : 0.0f;
#pragma unroll
        for (int o = 16; o > 0; o >>= 1)
            s += __shfl_down_sync(0xFFFFFFFFu, s, o);
        if (threadIdx.x == 0)
            out[0] = s * invN;
    }
}

extern "C" void kernel_launch(void* const* d_in, const int* in_sizes, int n_in,
                              void* d_out, int out_size) {
    const float* predict = (const float*)d_in[0];
    const float* label   = (const float*)d_in[1];
    float* out = (float*)d_out;

    int total  = in_sizes[0];          // B*7*7*26
    int ncells = total / 26;           // B*49
    int nblocks = (ncells + TPB - 1) / TPB;
    if (nblocks > MAX_BLOCKS) nblocks = MAX_BLOCKS;  // never hit for this shape

    float invN = 49.0f / (float)ncells;  // 1 / batch

    yolo_cell_kernel<<<nblocks, TPB>>>(predict, label, ncells);
    yolo_reduce_kernel<<<1, 1024>>>(out, nblocks, invN);
}